// round 1
// baseline (speedup 1.0000x reference)
#include <cuda_runtime.h>
#include <cstdint>

#define NN 100000
#define EE 600000
#define GG 1000
// EMB = 128

// ---------------- scratch (static device allocations; no cudaMalloc) ----------
__device__ float d_dinv[NN];                 // deg, then rsqrt(deg)
__device__ float d_g[(size_t)NN * 128];      // GEMM output / messages
__device__ float d_acc[(size_t)NN * 128];    // scatter accumulator
__device__ float d_pool[GG * 128];
__device__ float d_cnt[GG];

// ---------------- degree / norm ----------------------------------------------
__global__ void k_deg_init() {
    int i = blockIdx.x * blockDim.x + threadIdx.x;
    if (i < NN) d_dinv[i] = 1.0f;            // self-loop contributes 1
}
__global__ void k_deg_count(const int* __restrict__ dst) {
    int e = blockIdx.x * blockDim.x + threadIdx.x;
    if (e < EE) atomicAdd(&d_dinv[dst[e]], 1.0f);
}
__global__ void k_dinv() {
    int i = blockIdx.x * blockDim.x + threadIdx.x;
    if (i < NN) d_dinv[i] = rsqrtf(d_dinv[i]);   // deg >= 1 always
}

// ---------------- layer 0 GEMM: g = x @ W0  (K = 4) --------------------------
__global__ void k_gemm0(const float* __restrict__ x, const float* __restrict__ W0) {
    __shared__ float Ws[512];                // 4 x 128
    int t = threadIdx.x;
    Ws[t] = W0[t];
    Ws[t + 256] = W0[t + 256];
    __syncthreads();
    int c = t & 127;
    int n = blockIdx.x * 2 + (t >> 7);       // 2 nodes per 256-thread block
    const float* xr = x + n * 4;
    float x0 = xr[0], x1 = xr[1], x2 = xr[2], x3 = xr[3];
    float a = x0 * Ws[c] + x1 * Ws[128 + c] + x2 * Ws[256 + c] + x3 * Ws[384 + c];
    d_g[(size_t)n * 128 + c] = a;
}

// ---------------- main GEMM: g = relu(acc + b_prev) @ W  (128x128) -----------
// 32 nodes per block, 256 threads. Warp w -> nodes w*4..w*4+3, lane l -> cols 4l..4l+3.
// Uses Blackwell packed fma.rn.f32x2 (2 fp32 FMAs per instruction).
__global__ void k_gemm(const float* __restrict__ in, const float* __restrict__ W,
                       const float* __restrict__ bias, float* __restrict__ out) {
    extern __shared__ float sm[];
    float* Ws = sm;                 // 128*128 floats = 64 KB
    float* Ts = sm + 128 * 128;     // 32*128  floats = 16 KB
    int t = threadIdx.x;

    // load W (4096 float4, 16 per thread)
    const float4* W4 = (const float4*)W;
    float4* Ws4 = (float4*)Ws;
#pragma unroll
    for (int i = 0; i < 16; i++)
        Ws4[t + 256 * i] = __ldg(&W4[t + 256 * i]);

    // load 32-node tile, fusing bias + relu of previous layer
    size_t base = (size_t)blockIdx.x * 32 * 128;
    const float4* inp = (const float4*)(in + base);
    const float4* b4  = (const float4*)bias;
    float4* Ts4 = (float4*)Ts;
#pragma unroll
    for (int i = 0; i < 4; i++) {
        int idx = t * 4 + i;                 // float4 index within 1024
        float4 v  = inp[idx];
        float4 bb = b4[idx & 31];
        v.x = fmaxf(v.x + bb.x, 0.f);
        v.y = fmaxf(v.y + bb.y, 0.f);
        v.z = fmaxf(v.z + bb.z, 0.f);
        v.w = fmaxf(v.w + bb.w, 0.f);
        Ts4[idx] = v;
    }
    __syncthreads();

    int w = t >> 5, l = t & 31;
    unsigned long long a00 = 0ull, a01 = 0ull, a10 = 0ull, a11 = 0ull;
    unsigned long long a20 = 0ull, a21 = 0ull, a30 = 0ull, a31 = 0ull;
    const float* Trow = Ts + (w * 4) * 128;
    const float4* Wc = (const float4*)Ws + l;

#pragma unroll 4
    for (int k = 0; k < 128; k++) {
        float4 wv = Wc[k * 32];
        unsigned long long wp0, wp1;
        asm("mov.b64 %0, {%1,%2};" : "=l"(wp0) : "f"(wv.x), "f"(wv.y));
        asm("mov.b64 %0, {%1,%2};" : "=l"(wp1) : "f"(wv.z), "f"(wv.w));
        float t0 = Trow[k], t1 = Trow[128 + k], t2 = Trow[256 + k], t3 = Trow[384 + k];
        unsigned long long tp;
        asm("mov.b64 %0, {%1,%2};" : "=l"(tp) : "f"(t0), "f"(t0));
        asm("fma.rn.f32x2 %0, %1, %2, %0;" : "+l"(a00) : "l"(tp), "l"(wp0));
        asm("fma.rn.f32x2 %0, %1, %2, %0;" : "+l"(a01) : "l"(tp), "l"(wp1));
        asm("mov.b64 %0, {%1,%2};" : "=l"(tp) : "f"(t1), "f"(t1));
        asm("fma.rn.f32x2 %0, %1, %2, %0;" : "+l"(a10) : "l"(tp), "l"(wp0));
        asm("fma.rn.f32x2 %0, %1, %2, %0;" : "+l"(a11) : "l"(tp), "l"(wp1));
        asm("mov.b64 %0, {%1,%2};" : "=l"(tp) : "f"(t2), "f"(t2));
        asm("fma.rn.f32x2 %0, %1, %2, %0;" : "+l"(a20) : "l"(tp), "l"(wp0));
        asm("fma.rn.f32x2 %0, %1, %2, %0;" : "+l"(a21) : "l"(tp), "l"(wp1));
        asm("mov.b64 %0, {%1,%2};" : "=l"(tp) : "f"(t3), "f"(t3));
        asm("fma.rn.f32x2 %0, %1, %2, %0;" : "+l"(a30) : "l"(tp), "l"(wp0));
        asm("fma.rn.f32x2 %0, %1, %2, %0;" : "+l"(a31) : "l"(tp), "l"(wp1));
    }

    float4* o4 = (float4*)(out + base);
    unsigned long long lo[4] = {a00, a10, a20, a30};
    unsigned long long hi[4] = {a01, a11, a21, a31};
#pragma unroll
    for (int i = 0; i < 4; i++) {
        float4 r;
        asm("mov.b64 {%0,%1}, %2;" : "=f"(r.x), "=f"(r.y) : "l"(lo[i]));
        asm("mov.b64 {%0,%1}, %2;" : "=f"(r.z), "=f"(r.w) : "l"(hi[i]));
        o4[(w * 4 + i) * 32 + l] = r;
    }
}

// ---------------- self-loop init: acc = dinv^2 * g ---------------------------
__global__ void k_self() {
    int i = blockIdx.x * 256 + threadIdx.x;  // i < NN*32, exact grid
    int n = i >> 5;
    float di = d_dinv[n];
    float s = di * di;
    float4 v = ((const float4*)d_g)[i];
    v.x *= s; v.y *= s; v.z *= s; v.w *= s;
    ((float4*)d_acc)[i] = v;
}

// ---------------- edge scatter: acc[dst] += norm * g[src] --------------------
// One warp per edge; lane l handles float4 chunk l (128 floats / edge).
__global__ void k_scatter(const int* __restrict__ src, const int* __restrict__ dst) {
    int e = blockIdx.x * 8 + (threadIdx.x >> 5);   // exact: 75000 blocks
    int l = threadIdx.x & 31;
    int s = __ldg(&src[e]);
    int d = __ldg(&dst[e]);
    float nm = d_dinv[s] * d_dinv[d];
    float4 v = __ldg(((const float4*)d_g) + (s * 32 + l));
    float* p = d_acc + ((size_t)d * 128 + l * 4);
    asm volatile("red.global.add.v4.f32 [%0], {%1,%2,%3,%4};"
                 :: "l"(p), "f"(v.x * nm), "f"(v.y * nm), "f"(v.z * nm), "f"(v.w * nm)
                 : "memory");
}

// ---------------- pooling ------------------------------------------------------
__global__ void k_zero_pool() {
    int i = blockIdx.x * 256 + threadIdx.x;
    if (i < GG * 128) d_pool[i] = 0.f;
    if (i < GG) d_cnt[i] = 0.f;
}
__global__ void k_pool(const int* __restrict__ batch, const float* __restrict__ b3) {
    int i = blockIdx.x * 256 + threadIdx.x;  // exact: NN*32 threads
    int n = i >> 5;
    int l = i & 31;
    int g = __ldg(&batch[n]);
    float4 v  = ((const float4*)d_acc)[i];
    float4 bb = ((const float4*)b3)[l];
    v.x = fmaxf(v.x + bb.x, 0.f);
    v.y = fmaxf(v.y + bb.y, 0.f);
    v.z = fmaxf(v.z + bb.z, 0.f);
    v.w = fmaxf(v.w + bb.w, 0.f);
    float* p = d_pool + g * 128 + l * 4;
    asm volatile("red.global.add.v4.f32 [%0], {%1,%2,%3,%4};"
                 :: "l"(p), "f"(v.x), "f"(v.y), "f"(v.z), "f"(v.w) : "memory");
    if (l == 0) atomicAdd(&d_cnt[g], 1.0f);
}

// ---------------- final MLP: out = relu([pooled, xs] @ Wl1 + bl1) @ Wl2 + bl2 -
__global__ void k_mlp(const float* __restrict__ xs, const float* __restrict__ Wl1,
                      const float* __restrict__ bl1, const float* __restrict__ Wl2,
                      const float* __restrict__ bl2, float* __restrict__ out) {
    __shared__ float feat[132];
    __shared__ float part[64];
    int g = blockIdx.x, t = threadIdx.x;
    float inv = 1.0f / fmaxf(d_cnt[g], 1.0f);
    for (int i = t; i < 132; i += 64)
        feat[i] = (i < 128) ? d_pool[g * 128 + i] * inv : xs[g * 4 + (i - 128)];
    __syncthreads();
    float h = bl1[t];
#pragma unroll 4
    for (int i = 0; i < 132; i++) h = fmaf(feat[i], Wl1[i * 64 + t], h);
    h = fmaxf(h, 0.f);
    part[t] = h * Wl2[t];
    __syncthreads();
    if (t == 0) {
        float s = bl2[0];
#pragma unroll
        for (int j = 0; j < 64; j++) s += part[j];
        out[g] = s;
    }
}

// ---------------- launcher ----------------------------------------------------
extern "C" void kernel_launch(void* const* d_in, const int* in_sizes, int n_in,
                              void* d_out, int out_size) {
    const float* x     = (const float*)d_in[0];
    const int*   ei    = (const int*)d_in[1];
    const float* xs    = (const float*)d_in[2];
    const int*   batch = (const int*)d_in[3];
    const float* W0  = (const float*)d_in[4];
    const float* b0  = (const float*)d_in[5];
    const float* W1  = (const float*)d_in[6];
    const float* b1  = (const float*)d_in[7];
    const float* W2  = (const float*)d_in[8];
    const float* b2  = (const float*)d_in[9];
    const float* W3  = (const float*)d_in[10];
    const float* b3  = (const float*)d_in[11];
    const float* Wl1 = (const float*)d_in[12];
    const float* bl1 = (const float*)d_in[13];
    const float* Wl2 = (const float*)d_in[14];
    const float* bl2 = (const float*)d_in[15];
    float* out = (float*)d_out;

    const int* srcp = ei;        // edge_index[0]
    const int* dstp = ei + EE;   // edge_index[1]

    // 80 KB dynamic smem for the main GEMM (W 64KB + tile 16KB). Not a stream
    // op; idempotent, safe under graph capture.
    cudaFuncSetAttribute(k_gemm, cudaFuncAttributeMaxDynamicSharedMemorySize, 81920);

    float *gp, *accp;
    cudaGetSymbolAddress((void**)&gp, d_g);
    cudaGetSymbolAddress((void**)&accp, d_acc);

    // degree / normalization
    k_deg_init<<<(NN + 255) / 256, 256>>>();
    k_deg_count<<<(EE + 255) / 256, 256>>>(dstp);
    k_dinv<<<(NN + 255) / 256, 256>>>();

    // layer 0
    k_gemm0<<<NN / 2, 256>>>(x, W0);
    k_self<<<NN * 32 / 256, 256>>>();
    k_scatter<<<EE / 8, 256>>>(srcp, dstp);

    // layers 1..3 (bias+relu of previous layer fused into GEMM tile load)
    k_gemm<<<NN / 32, 256, 81920>>>(accp, W1, b0, gp);
    k_self<<<NN * 32 / 256, 256>>>();
    k_scatter<<<EE / 8, 256>>>(srcp, dstp);

    k_gemm<<<NN / 32, 256, 81920>>>(accp, W2, b1, gp);
    k_self<<<NN * 32 / 256, 256>>>();
    k_scatter<<<EE / 8, 256>>>(srcp, dstp);

    k_gemm<<<NN / 32, 256, 81920>>>(accp, W3, b2, gp);
    k_self<<<NN * 32 / 256, 256>>>();
    k_scatter<<<EE / 8, 256>>>(srcp, dstp);

    // pool + head (bias+relu of layer 3 fused into pooling)
    k_zero_pool<<<(GG * 128 + 255) / 256, 256>>>();
    k_pool<<<NN * 32 / 256, 256>>>(batch, b3);
    k_mlp<<<GG, 64>>>(xs, Wl1, bl1, Wl2, bl2, out);
}

// round 3
// speedup vs baseline: 1.1691x; 1.1691x over previous
#include <cuda_runtime.h>
#include <cuda_bf16.h>
#include <cstdint>

#define NN 100000
#define EE 600000
#define GG 1000
#define GTILES 1563   // ceil(NN/64)

// ---------------- static device scratch --------------------------------------
__device__ float d_dinv[NN];
__device__ float d_g[(size_t)NN * 128];      // p = dinv * (h @ W)
__device__ float d_acc[(size_t)NN * 128];    // s = p[v] + sum p[src]
__device__ float d_pool[GG * 128];
__device__ float d_pcnt[GG];
__device__ int   d_cnti[NN];
__device__ int   d_off[NN + 1];
__device__ int   d_cur[NN];
__device__ int   d_csr[EE];

// ---------------- helpers ------------------------------------------------------
__device__ __forceinline__ uint32_t smem_u32(const void* p) {
    uint32_t a;
    asm("{ .reg .u64 t; cvta.to.shared.u64 t, %1; cvt.u32.u64 %0, t; }" : "=r"(a) : "l"(p));
    return a;
}
#define LDM_X4(r, addr) \
    asm volatile("ldmatrix.sync.aligned.m8n8.x4.shared.b16 {%0,%1,%2,%3}, [%4];" \
        : "=r"((r)[0]), "=r"((r)[1]), "=r"((r)[2]), "=r"((r)[3]) : "r"(addr))

__device__ __forceinline__ void mma_bf16(float* c, const uint32_t* a, const uint32_t* b) {
    asm volatile("mma.sync.aligned.m16n8k16.row.col.f32.bf16.bf16.f32 "
        "{%0,%1,%2,%3}, {%4,%5,%6,%7}, {%8,%9}, {%0,%1,%2,%3};"
        : "+f"(c[0]), "+f"(c[1]), "+f"(c[2]), "+f"(c[3])
        : "r"(a[0]), "r"(a[1]), "r"(a[2]), "r"(a[3]), "r"(b[0]), "r"(b[1]));
}

// ---------------- degree / CSR ------------------------------------------------
__global__ void k_zero_cnt() {
    int i = blockIdx.x * 256 + threadIdx.x;
    if (i < NN) d_cnti[i] = 0;
}
__global__ void k_count(const int* __restrict__ dst) {
    int e = blockIdx.x * 256 + threadIdx.x;
    if (e < EE) atomicAdd(&d_cnti[dst[e]], 1);
}
__global__ void k_dinv() {
    int i = blockIdx.x * 256 + threadIdx.x;
    if (i < NN) d_dinv[i] = rsqrtf((float)(d_cnti[i] + 1));
}
__global__ void k_scan() {            // 1 block, 1024 threads
    __shared__ int s[1024];
    const int CH = 98;                // 1024*98 >= NN
    int t = threadIdx.x;
    int beg = t * CH, end = beg + CH; if (end > NN) end = NN;
    int sum = 0;
    for (int i = beg; i < end; i++) sum += d_cnti[i];
    s[t] = sum;
    __syncthreads();
    for (int off = 1; off < 1024; off <<= 1) {
        int v = (t >= off) ? s[t - off] : 0;
        __syncthreads();
        s[t] += v;
        __syncthreads();
    }
    int run = s[t] - sum;             // exclusive prefix
    for (int i = beg; i < end; i++) {
        d_off[i] = run; d_cur[i] = run;
        run += d_cnti[i];
    }
    if (beg < NN && end == NN) d_off[NN] = run;
}
__global__ void k_fill(const int* __restrict__ src, const int* __restrict__ dst) {
    int e = blockIdx.x * 256 + threadIdx.x;
    if (e < EE) {
        int pos = atomicAdd(&d_cur[dst[e]], 1);
        d_csr[pos] = src[e];
    }
}

// ---------------- layer 0: p0 = dinv * (x @ W0), K=4 --------------------------
__global__ void k_gemm0(const float* __restrict__ x, const float* __restrict__ W0) {
    int t = threadIdx.x;
    int j = t & 31;                   // float4 column group
    float w[16];
#pragma unroll
    for (int k = 0; k < 4; k++)
#pragma unroll
        for (int c = 0; c < 4; c++)
            w[k * 4 + c] = __ldg(&W0[k * 128 + j * 4 + c]);
    int gw = blockIdx.x * 8 + (t >> 5);
    for (int n = gw; n < NN; n += gridDim.x * 8) {
        float4 xv = __ldg((const float4*)x + n);
        float di = d_dinv[n];
        float4 r;
        r.x = di * (xv.x * w[0] + xv.y * w[4] + xv.z * w[8]  + xv.w * w[12]);
        r.y = di * (xv.x * w[1] + xv.y * w[5] + xv.z * w[9]  + xv.w * w[13]);
        r.z = di * (xv.x * w[2] + xv.y * w[6] + xv.z * w[10] + xv.w * w[14]);
        r.w = di * (xv.x * w[3] + xv.y * w[7] + xv.z * w[11] + xv.w * w[15]);
        ((float4*)d_g)[(size_t)n * 32 + j] = r;
    }
}

// ---------------- CSR gather: s[v] = p[v] + sum_{u->v} p[u] -------------------
__global__ void k_gather() {          // grid NN/8 exact, block 256
    int v = blockIdx.x * 8 + (threadIdx.x >> 5);
    int l = threadIdx.x & 31;
    const float4* P = (const float4*)d_g;
    float4 a = P[(size_t)v * 32 + l];
    int beg = d_off[v], end = d_off[v + 1];
    for (int e = beg; e < end; e++) {
        int s = __ldg(&d_csr[e]);
        float4 x = __ldg(&P[(size_t)s * 32 + l]);
        a.x += x.x; a.y += x.y; a.z += x.z; a.w += x.w;
    }
    ((float4*)d_acc)[(size_t)v * 32 + l] = a;
}

// ---------------- HMMA GEMM: p = dinv * (relu(dinv*s + b) @ W) ----------------
// 64 rows x 128 cols per block, 256 threads (8 warps = 4 row-strips x 2 col-halves).
// fp32 via 3x bf16 products. A/B in padded smem (pitch 136 bf16), ldmatrix feeds.
#define PITCH 136
#define A_HI 0
#define A_LO 17408
#define B_HI 34816
#define B_LO 69632
#define SMEM_MMA 104448

__global__ void __launch_bounds__(256) k_gemm_mma(const float* __restrict__ in,
                                                  const float* __restrict__ W,
                                                  const float* __restrict__ bias,
                                                  float* __restrict__ out) {
    extern __shared__ char smb[];
    uint32_t sbase = smem_u32(smb);
    int t = threadIdx.x, w = t >> 5, l = t & 31;

    // ---- W -> bf16 hi/lo, transposed to [n][k], pitch 136 ----
    for (int idx = t; idx < 128 * 128; idx += 256) {
        int n = idx & 127, k = idx >> 7;
        float wv = __ldg(&W[k * 128 + n]);
        __nv_bfloat16 hb = __float2bfloat16_rn(wv);
        __nv_bfloat16 lb = __float2bfloat16_rn(wv - __bfloat162float(hb));
        int off = (n * PITCH + k) * 2;
        *(unsigned short*)(smb + B_HI + off) = __bfloat16_as_ushort(hb);
        *(unsigned short*)(smb + B_LO + off) = __bfloat16_as_ushort(lb);
    }

    // ---- A tile: val = relu(dinv*s + b), split bf16 hi/lo ----
    int tile = blockIdx.x;
    for (int idx = t; idx < 64 * 32; idx += 256) {
        int r = idx >> 5, q = idx & 31;
        int m = tile * 64 + r;
        float4 v = make_float4(0.f, 0.f, 0.f, 0.f);
        float di = 0.f;
        if (m < NN) {
            v = __ldg((const float4*)in + (size_t)m * 32 + q);
            di = d_dinv[m];
        }
        float4 bb = __ldg((const float4*)bias + q);
        float a0 = fmaxf(fmaf(di, v.x, bb.x), 0.f);
        float a1 = fmaxf(fmaf(di, v.y, bb.y), 0.f);
        float a2 = fmaxf(fmaf(di, v.z, bb.z), 0.f);
        float a3 = fmaxf(fmaf(di, v.w, bb.w), 0.f);
        __nv_bfloat16 h0 = __float2bfloat16_rn(a0), h1 = __float2bfloat16_rn(a1);
        __nv_bfloat16 h2 = __float2bfloat16_rn(a2), h3 = __float2bfloat16_rn(a3);
        __nv_bfloat16 l0 = __float2bfloat16_rn(a0 - __bfloat162float(h0));
        __nv_bfloat16 l1 = __float2bfloat16_rn(a1 - __bfloat162float(h1));
        __nv_bfloat16 l2 = __float2bfloat16_rn(a2 - __bfloat162float(h2));
        __nv_bfloat16 l3 = __float2bfloat16_rn(a3 - __bfloat162float(h3));
        uint2 hp, lp;
        hp.x = (uint32_t)__bfloat16_as_ushort(h0) | ((uint32_t)__bfloat16_as_ushort(h1) << 16);
        hp.y = (uint32_t)__bfloat16_as_ushort(h2) | ((uint32_t)__bfloat16_as_ushort(h3) << 16);
        lp.x = (uint32_t)__bfloat16_as_ushort(l0) | ((uint32_t)__bfloat16_as_ushort(l1) << 16);
        lp.y = (uint32_t)__bfloat16_as_ushort(l2) | ((uint32_t)__bfloat16_as_ushort(l3) << 16);
        int off = (r * PITCH + q * 4) * 2;
        *(uint2*)(smb + A_HI + off) = hp;
        *(uint2*)(smb + A_LO + off) = lp;
    }
    __syncthreads();

    // ---- fragment addresses ----
    int rs = (w >> 1) * 16;          // row strip within tile
    int cb = (w & 1) * 64;           // col half
    int arow = rs + (l & 7) + ((l >> 3) & 1) * 8;
    int acol8 = (l >> 4) * 8;
    uint32_t a_hi = sbase + A_HI + (arow * PITCH + acol8) * 2;
    uint32_t a_lo = sbase + A_LO + (arow * PITCH + acol8) * 2;
    int brow = (l & 7) + (l >> 4) * 8;       // local n within 16-pair
    int bk8  = ((l >> 3) & 1) * 8;

    float acc[32];
#pragma unroll
    for (int i = 0; i < 32; i++) acc[i] = 0.f;

#pragma unroll
    for (int kb = 0; kb < 8; kb++) {
        int k0 = kb * 16;
        uint32_t ah[4], al[4];
        LDM_X4(ah, a_hi + k0 * 2);
        LDM_X4(al, a_lo + k0 * 2);
#pragma unroll
        for (int np = 0; np < 4; np++) {
            int nb = cb + np * 16;
            uint32_t boff = (uint32_t)(((nb + brow) * PITCH + k0 + bk8) * 2);
            uint32_t bh[4], bl[4];
            LDM_X4(bh, sbase + B_HI + boff);
            LDM_X4(bl, sbase + B_LO + boff);
            float* c = acc + np * 8;
            mma_bf16(c,     ah, bh);
            mma_bf16(c,     ah, bl);
            mma_bf16(c,     al, bh);
            mma_bf16(c + 4, ah, bh + 2);
            mma_bf16(c + 4, ah, bl + 2);
            mma_bf16(c + 4, al, bh + 2);
        }
    }

    // ---- epilogue: scale rows by dinv, store fp32 ----
    int r0 = tile * 64 + rs + (l >> 2);
    int r1 = r0 + 8;
    float d0 = (r0 < NN) ? d_dinv[r0] : 0.f;
    float d1 = (r1 < NN) ? d_dinv[r1] : 0.f;
#pragma unroll
    for (int nt = 0; nt < 8; nt++) {
        int col = cb + nt * 8 + (l & 3) * 2;
        float* a = acc + nt * 4;
        if (r0 < NN) *(float2*)&out[(size_t)r0 * 128 + col] = make_float2(a[0] * d0, a[1] * d0);
        if (r1 < NN) *(float2*)&out[(size_t)r1 * 128 + col] = make_float2(a[2] * d1, a[3] * d1);
    }
}

// ---------------- pooling -----------------------------------------------------
__global__ void k_zero_pool() {
    int i = blockIdx.x * 256 + threadIdx.x;
    if (i < GG * 128) d_pool[i] = 0.f;
    if (i < GG) d_pcnt[i] = 0.f;
}
__global__ void k_pool(const int* __restrict__ batch, const float* __restrict__ b3) {
    int i = blockIdx.x * 256 + threadIdx.x;    // exact NN*32
    int n = i >> 5;
    int l = i & 31;
    int g = __ldg(&batch[n]);
    float di = d_dinv[n];
    float4 v  = ((const float4*)d_acc)[i];
    float4 bb = __ldg((const float4*)b3 + l);
    v.x = fmaxf(fmaf(di, v.x, bb.x), 0.f);
    v.y = fmaxf(fmaf(di, v.y, bb.y), 0.f);
    v.z = fmaxf(fmaf(di, v.z, bb.z), 0.f);
    v.w = fmaxf(fmaf(di, v.w, bb.w), 0.f);
    float* p = d_pool + g * 128 + l * 4;
    asm volatile("red.global.add.v4.f32 [%0], {%1,%2,%3,%4};"
                 :: "l"(p), "f"(v.x), "f"(v.y), "f"(v.z), "f"(v.w) : "memory");
    if (l == 0) atomicAdd(&d_pcnt[g], 1.0f);
}

// ---------------- final MLP ----------------------------------------------------
__global__ void k_mlp(const float* __restrict__ xs, const float* __restrict__ Wl1,
                      const float* __restrict__ bl1, const float* __restrict__ Wl2,
                      const float* __restrict__ bl2, float* __restrict__ out) {
    __shared__ float feat[132];
    __shared__ float part[64];
    int g = blockIdx.x, t = threadIdx.x;
    float inv = 1.0f / fmaxf(d_pcnt[g], 1.0f);
    for (int i = t; i < 132; i += 64)
        feat[i] = (i < 128) ? d_pool[g * 128 + i] * inv : xs[g * 4 + (i - 128)];
    __syncthreads();
    float h = bl1[t];
#pragma unroll 4
    for (int i = 0; i < 132; i++) h = fmaf(feat[i], Wl1[i * 64 + t], h);
    h = fmaxf(h, 0.f);
    part[t] = h * Wl2[t];
    __syncthreads();
    if (t == 0) {
        float s = bl2[0];
#pragma unroll
        for (int j = 0; j < 64; j++) s += part[j];
        out[g] = s;
    }
}

// ---------------- launcher ----------------------------------------------------
extern "C" void kernel_launch(void* const* d_in, const int* in_sizes, int n_in,
                              void* d_out, int out_size) {
    const float* x     = (const float*)d_in[0];
    const int*   ei    = (const int*)d_in[1];
    const float* xs    = (const float*)d_in[2];
    const int*   batch = (const int*)d_in[3];
    const float* W0  = (const float*)d_in[4];
    const float* b0  = (const float*)d_in[5];
    const float* W1  = (const float*)d_in[6];
    const float* b1  = (const float*)d_in[7];
    const float* W2  = (const float*)d_in[8];
    const float* b2  = (const float*)d_in[9];
    const float* W3  = (const float*)d_in[10];
    const float* b3  = (const float*)d_in[11];
    const float* Wl1 = (const float*)d_in[12];
    const float* bl1 = (const float*)d_in[13];
    const float* Wl2 = (const float*)d_in[14];
    const float* bl2 = (const float*)d_in[15];
    float* out = (float*)d_out;

    const int* srcp = ei;
    const int* dstp = ei + EE;

    cudaFuncSetAttribute(k_gemm_mma, cudaFuncAttributeMaxDynamicSharedMemorySize, SMEM_MMA);

    float *gp, *accp;
    cudaGetSymbolAddress((void**)&gp, d_g);
    cudaGetSymbolAddress((void**)&accp, d_acc);

    // degree + CSR build (reused by all 4 layers)
    k_zero_cnt<<<(NN + 255) / 256, 256>>>();
    k_count<<<(EE + 255) / 256, 256>>>(dstp);
    k_dinv<<<(NN + 255) / 256, 256>>>();
    k_scan<<<1, 1024>>>();
    k_fill<<<(EE + 255) / 256, 256>>>(srcp, dstp);

    // layer 0
    k_gemm0<<<1024, 256>>>(x, W0);
    k_gather<<<NN / 8, 256>>>();

    // layers 1..3 (bias+relu+dinv of prev layer fused into GEMM input transform)
    k_gemm_mma<<<GTILES, 256, SMEM_MMA>>>(accp, W1, b0, gp);
    k_gather<<<NN / 8, 256>>>();

    k_gemm_mma<<<GTILES, 256, SMEM_MMA>>>(accp, W2, b1, gp);
    k_gather<<<NN / 8, 256>>>();

    k_gemm_mma<<<GTILES, 256, SMEM_MMA>>>(accp, W3, b2, gp);
    k_gather<<<NN / 8, 256>>>();

    // pool + head
    k_zero_pool<<<(GG * 128 + 255) / 256, 256>>>();
    k_pool<<<NN * 32 / 256, 256>>>(batch, b3);
    k_mlp<<<GG, 64>>>(xs, Wl1, bl1, Wl2, bl2, out);
}

// round 4
// speedup vs baseline: 1.7983x; 1.5382x over previous
#include <cuda_runtime.h>
#include <cuda_bf16.h>
#include <cstdint>

#define NN 100000
#define EE 600000
#define GG 1000
#define GTILES 1563   // ceil(NN/64)
#define NB 391        // ceil(NN/256)

// ---------------- static device scratch --------------------------------------
__device__ float d_dinv[NN];
__device__ float d_g[(size_t)NN * 128];      // p = dinv * (h @ W)
__device__ float d_acc[(size_t)NN * 128];    // s = p[v] + sum p[src]
__device__ float d_pool[GG * 128];
__device__ float d_pcnt[GG];
__device__ int   d_cnti[NN];
__device__ int   d_off[NN + 1];
__device__ int   d_cur[NN];
__device__ int   d_csr[EE];
__device__ int   d_bsum[NB + 1];
__device__ __nv_bfloat16 d_whi[128 * 128];   // W^T bf16 high, [n][k]
__device__ __nv_bfloat16 d_wlo[128 * 128];   // W^T bf16 low

// ---------------- helpers ------------------------------------------------------
__device__ __forceinline__ uint32_t smem_u32(const void* p) {
    uint32_t a;
    asm("{ .reg .u64 t; cvta.to.shared.u64 t, %1; cvt.u32.u64 %0, t; }" : "=r"(a) : "l"(p));
    return a;
}
#define LDM_X4(r, addr) \
    asm volatile("ldmatrix.sync.aligned.m8n8.x4.shared.b16 {%0,%1,%2,%3}, [%4];" \
        : "=r"((r)[0]), "=r"((r)[1]), "=r"((r)[2]), "=r"((r)[3]) : "r"(addr))

__device__ __forceinline__ void mma_bf16(float* c, const uint32_t* a, const uint32_t* b) {
    asm volatile("mma.sync.aligned.m16n8k16.row.col.f32.bf16.bf16.f32 "
        "{%0,%1,%2,%3}, {%4,%5,%6,%7}, {%8,%9}, {%0,%1,%2,%3};"
        : "+f"(c[0]), "+f"(c[1]), "+f"(c[2]), "+f"(c[3])
        : "r"(a[0]), "r"(a[1]), "r"(a[2]), "r"(a[3]), "r"(b[0]), "r"(b[1]));
}

// ---------------- degree / CSR ------------------------------------------------
__global__ void k_zero_cnt() {
    int i = blockIdx.x * 256 + threadIdx.x;
    if (i < NN) d_cnti[i] = 0;
}
__global__ void k_count(const int* __restrict__ dst) {
    int e = blockIdx.x * 256 + threadIdx.x;
    if (e < EE) atomicAdd(&d_cnti[dst[e]], 1);
}
__global__ void k_dinv() {
    int i = blockIdx.x * 256 + threadIdx.x;
    if (i < NN) d_dinv[i] = rsqrtf((float)(d_cnti[i] + 1));
}
// 3-phase scan: local block scan -> scan of block sums -> add offsets.
__global__ void k_scan1() {
    __shared__ int s[256];
    int b = blockIdx.x, t = threadIdx.x;
    int i = b * 256 + t;
    int v = (i < NN) ? d_cnti[i] : 0;
    s[t] = v;
    __syncthreads();
#pragma unroll
    for (int off = 1; off < 256; off <<= 1) {
        int x = (t >= off) ? s[t - off] : 0;
        __syncthreads();
        s[t] += x;
        __syncthreads();
    }
    if (i < NN) d_off[i] = s[t] - v;        // block-local exclusive
    if (t == 255) d_bsum[b] = s[255];       // block total
}
__global__ void k_scan2() {   // 1 block, 512 threads (NB=391 <= 512)
    __shared__ int s[512];
    int t = threadIdx.x;
    int v = (t < NB) ? d_bsum[t] : 0;
    s[t] = v;
    __syncthreads();
#pragma unroll
    for (int off = 1; off < 512; off <<= 1) {
        int x = (t >= off) ? s[t - off] : 0;
        __syncthreads();
        s[t] += x;
        __syncthreads();
    }
    if (t < NB) d_bsum[t] = s[t] - v;       // exclusive block offsets
}
__global__ void k_scan3() {
    int b = blockIdx.x, t = threadIdx.x;
    int i = b * 256 + t;
    if (i < NN) {
        int o = d_off[i] + d_bsum[b];
        d_off[i] = o;
        d_cur[i] = o;
    }
    if (i == 0) d_off[NN] = EE;
}
__global__ void k_fill(const int* __restrict__ src, const int* __restrict__ dst) {
    int e = blockIdx.x * 256 + threadIdx.x;
    if (e < EE) {
        int pos = atomicAdd(&d_cur[dst[e]], 1);
        d_csr[pos] = src[e];
    }
}

// ---------------- W -> bf16 hi/lo, transposed [n][k] --------------------------
__global__ void k_wconv(const float* __restrict__ W) {
    int idx = blockIdx.x * 256 + threadIdx.x;   // 64 blocks x 256 = 16384
    int n = idx & 127, k = idx >> 7;
    float wv = __ldg(&W[k * 128 + n]);
    __nv_bfloat16 hb = __float2bfloat16_rn(wv);
    __nv_bfloat16 lb = __float2bfloat16_rn(wv - __bfloat162float(hb));
    d_whi[n * 128 + k] = hb;
    d_wlo[n * 128 + k] = lb;
}

// ---------------- layer 0: p0 = dinv * (x @ W0), K=4 --------------------------
__global__ void k_gemm0(const float* __restrict__ x, const float* __restrict__ W0) {
    int t = threadIdx.x;
    int j = t & 31;                   // float4 column group
    float w[16];
#pragma unroll
    for (int k = 0; k < 4; k++)
#pragma unroll
        for (int c = 0; c < 4; c++)
            w[k * 4 + c] = __ldg(&W0[k * 128 + j * 4 + c]);
    int gw = blockIdx.x * 8 + (t >> 5);
    for (int n = gw; n < NN; n += gridDim.x * 8) {
        float4 xv = __ldg((const float4*)x + n);
        float di = d_dinv[n];
        float4 r;
        r.x = di * (xv.x * w[0] + xv.y * w[4] + xv.z * w[8]  + xv.w * w[12]);
        r.y = di * (xv.x * w[1] + xv.y * w[5] + xv.z * w[9]  + xv.w * w[13]);
        r.z = di * (xv.x * w[2] + xv.y * w[6] + xv.z * w[10] + xv.w * w[14]);
        r.w = di * (xv.x * w[3] + xv.y * w[7] + xv.z * w[11] + xv.w * w[15]);
        ((float4*)d_g)[(size_t)n * 32 + j] = r;
    }
}

// ---------------- CSR gather: s[v] = p[v] + sum_{u->v} p[u] -------------------
__global__ void k_gather() {          // grid NN/8 exact, block 256
    int v = blockIdx.x * 8 + (threadIdx.x >> 5);
    int l = threadIdx.x & 31;
    const float4* P = (const float4*)d_g;
    float4 a = P[(size_t)v * 32 + l];
    int beg = d_off[v], end = d_off[v + 1];
    for (int e = beg; e < end; e++) {
        int s = __ldg(&d_csr[e]);
        float4 x = __ldg(&P[(size_t)s * 32 + l]);
        a.x += x.x; a.y += x.y; a.z += x.z; a.w += x.w;
    }
    ((float4*)d_acc)[(size_t)v * 32 + l] = a;
}

// ---------------- HMMA GEMM: p = dinv * (relu(dinv*s + b) @ W) ----------------
// 64 rows x 128 cols per block, 256 threads (8 warps = 4 row-strips x 2 col-halves).
// fp32 via 3x bf16 products. A/B in padded smem (pitch 136 bf16), ldmatrix feeds.
#define PITCH 136
#define A_HI 0
#define A_LO 17408
#define B_HI 34816
#define B_LO 69632
#define SMEM_MMA 104448

__global__ void __launch_bounds__(256) k_gemm_mma(const float* __restrict__ in,
                                                  const float* __restrict__ bias,
                                                  float* __restrict__ out) {
    extern __shared__ char smb[];
    uint32_t sbase = smem_u32(smb);
    int t = threadIdx.x, w = t >> 5, l = t & 31;

    // ---- copy pre-converted W hi/lo into padded smem (16B chunks) ----
    const uint4* WH = (const uint4*)d_whi;     // 2048 x uint4 (8 bf16 each)
    const uint4* WL = (const uint4*)d_wlo;
#pragma unroll
    for (int i = t; i < 2048; i += 256) {
        int n = i >> 4, k8 = (i & 15) * 8;
        int off = (n * PITCH + k8) * 2;
        *(uint4*)(smb + B_HI + off) = __ldg(&WH[i]);
        *(uint4*)(smb + B_LO + off) = __ldg(&WL[i]);
    }

    // ---- A tile: val = relu(dinv*s + b), split bf16 hi/lo ----
    int tile = blockIdx.x;
    for (int idx = t; idx < 64 * 32; idx += 256) {
        int r = idx >> 5, q = idx & 31;
        int m = tile * 64 + r;
        float4 v = make_float4(0.f, 0.f, 0.f, 0.f);
        float di = 0.f;
        if (m < NN) {
            v = __ldg((const float4*)in + (size_t)m * 32 + q);
            di = d_dinv[m];
        }
        float4 bb = __ldg((const float4*)bias + q);
        float a0 = fmaxf(fmaf(di, v.x, bb.x), 0.f);
        float a1 = fmaxf(fmaf(di, v.y, bb.y), 0.f);
        float a2 = fmaxf(fmaf(di, v.z, bb.z), 0.f);
        float a3 = fmaxf(fmaf(di, v.w, bb.w), 0.f);
        __nv_bfloat16 h0 = __float2bfloat16_rn(a0), h1 = __float2bfloat16_rn(a1);
        __nv_bfloat16 h2 = __float2bfloat16_rn(a2), h3 = __float2bfloat16_rn(a3);
        __nv_bfloat16 l0 = __float2bfloat16_rn(a0 - __bfloat162float(h0));
        __nv_bfloat16 l1 = __float2bfloat16_rn(a1 - __bfloat162float(h1));
        __nv_bfloat16 l2 = __float2bfloat16_rn(a2 - __bfloat162float(h2));
        __nv_bfloat16 l3 = __float2bfloat16_rn(a3 - __bfloat162float(h3));
        uint2 hp, lp;
        hp.x = (uint32_t)__bfloat16_as_ushort(h0) | ((uint32_t)__bfloat16_as_ushort(h1) << 16);
        hp.y = (uint32_t)__bfloat16_as_ushort(h2) | ((uint32_t)__bfloat16_as_ushort(h3) << 16);
        lp.x = (uint32_t)__bfloat16_as_ushort(l0) | ((uint32_t)__bfloat16_as_ushort(l1) << 16);
        lp.y = (uint32_t)__bfloat16_as_ushort(l2) | ((uint32_t)__bfloat16_as_ushort(l3) << 16);
        int off = (r * PITCH + q * 4) * 2;
        *(uint2*)(smb + A_HI + off) = hp;
        *(uint2*)(smb + A_LO + off) = lp;
    }
    __syncthreads();

    // ---- fragment addresses ----
    int rs = (w >> 1) * 16;          // row strip within tile
    int cb = (w & 1) * 64;           // col half
    int arow = rs + (l & 7) + ((l >> 3) & 1) * 8;
    int acol8 = (l >> 4) * 8;
    uint32_t a_hi = sbase + A_HI + (arow * PITCH + acol8) * 2;
    uint32_t a_lo = sbase + A_LO + (arow * PITCH + acol8) * 2;
    int brow = (l & 7) + (l >> 4) * 8;       // local n within 16-pair
    int bk8  = ((l >> 3) & 1) * 8;

    float acc[32];
#pragma unroll
    for (int i = 0; i < 32; i++) acc[i] = 0.f;

#pragma unroll
    for (int kb = 0; kb < 8; kb++) {
        int k0 = kb * 16;
        uint32_t ah[4], al[4];
        LDM_X4(ah, a_hi + k0 * 2);
        LDM_X4(al, a_lo + k0 * 2);
#pragma unroll
        for (int np = 0; np < 4; np++) {
            int nb = cb + np * 16;
            uint32_t boff = (uint32_t)(((nb + brow) * PITCH + k0 + bk8) * 2);
            uint32_t bh[4], bl[4];
            LDM_X4(bh, sbase + B_HI + boff);
            LDM_X4(bl, sbase + B_LO + boff);
            float* c = acc + np * 8;
            mma_bf16(c,     ah, bh);
            mma_bf16(c,     ah, bl);
            mma_bf16(c,     al, bh);
            mma_bf16(c + 4, ah, bh + 2);
            mma_bf16(c + 4, ah, bl + 2);
            mma_bf16(c + 4, al, bh + 2);
        }
    }

    // ---- epilogue: scale rows by dinv, store fp32 ----
    int r0 = tile * 64 + rs + (l >> 2);
    int r1 = r0 + 8;
    float d0 = (r0 < NN) ? d_dinv[r0] : 0.f;
    float d1 = (r1 < NN) ? d_dinv[r1] : 0.f;
#pragma unroll
    for (int nt = 0; nt < 8; nt++) {
        int col = cb + nt * 8 + (l & 3) * 2;
        float* a = acc + nt * 4;
        if (r0 < NN) *(float2*)&out[(size_t)r0 * 128 + col] = make_float2(a[0] * d0, a[1] * d0);
        if (r1 < NN) *(float2*)&out[(size_t)r1 * 128 + col] = make_float2(a[2] * d1, a[3] * d1);
    }
}

// ---------------- pooling -----------------------------------------------------
__global__ void k_zero_pool() {
    int i = blockIdx.x * 256 + threadIdx.x;
    if (i < GG * 128) d_pool[i] = 0.f;
    if (i < GG) d_pcnt[i] = 0.f;
}
__global__ void k_pool(const int* __restrict__ batch, const float* __restrict__ b3) {
    int i = blockIdx.x * 256 + threadIdx.x;    // exact NN*32
    int n = i >> 5;
    int l = i & 31;
    int g = __ldg(&batch[n]);
    float di = d_dinv[n];
    float4 v  = ((const float4*)d_acc)[i];
    float4 bb = __ldg((const float4*)b3 + l);
    v.x = fmaxf(fmaf(di, v.x, bb.x), 0.f);
    v.y = fmaxf(fmaf(di, v.y, bb.y), 0.f);
    v.z = fmaxf(fmaf(di, v.z, bb.z), 0.f);
    v.w = fmaxf(fmaf(di, v.w, bb.w), 0.f);
    float* p = d_pool + g * 128 + l * 4;
    asm volatile("red.global.add.v4.f32 [%0], {%1,%2,%3,%4};"
                 :: "l"(p), "f"(v.x), "f"(v.y), "f"(v.z), "f"(v.w) : "memory");
    if (l == 0) atomicAdd(&d_pcnt[g], 1.0f);
}

// ---------------- final MLP ----------------------------------------------------
__global__ void k_mlp(const float* __restrict__ xs, const float* __restrict__ Wl1,
                      const float* __restrict__ bl1, const float* __restrict__ Wl2,
                      const float* __restrict__ bl2, float* __restrict__ out) {
    __shared__ float feat[132];
    __shared__ float part[64];
    int g = blockIdx.x, t = threadIdx.x;
    float inv = 1.0f / fmaxf(d_pcnt[g], 1.0f);
    for (int i = t; i < 132; i += 64)
        feat[i] = (i < 128) ? d_pool[g * 128 + i] * inv : xs[g * 4 + (i - 128)];
    __syncthreads();
    float h = bl1[t];
#pragma unroll 4
    for (int i = 0; i < 132; i++) h = fmaf(feat[i], Wl1[i * 64 + t], h);
    h = fmaxf(h, 0.f);
    part[t] = h * Wl2[t];
    __syncthreads();
    if (t == 0) {
        float s = bl2[0];
#pragma unroll
        for (int j = 0; j < 64; j++) s += part[j];
        out[g] = s;
    }
}

// ---------------- launcher ----------------------------------------------------
extern "C" void kernel_launch(void* const* d_in, const int* in_sizes, int n_in,
                              void* d_out, int out_size) {
    const float* x     = (const float*)d_in[0];
    const int*   ei    = (const int*)d_in[1];
    const float* xs    = (const float*)d_in[2];
    const int*   batch = (const int*)d_in[3];
    const float* W0  = (const float*)d_in[4];
    const float* b0  = (const float*)d_in[5];
    const float* W1  = (const float*)d_in[6];
    const float* b1  = (const float*)d_in[7];
    const float* W2  = (const float*)d_in[8];
    const float* b2  = (const float*)d_in[9];
    const float* W3  = (const float*)d_in[10];
    const float* b3  = (const float*)d_in[11];
    const float* Wl1 = (const float*)d_in[12];
    const float* bl1 = (const float*)d_in[13];
    const float* Wl2 = (const float*)d_in[14];
    const float* bl2 = (const float*)d_in[15];
    float* out = (float*)d_out;

    const int* srcp = ei;
    const int* dstp = ei + EE;

    cudaFuncSetAttribute(k_gemm_mma, cudaFuncAttributeMaxDynamicSharedMemorySize, SMEM_MMA);

    float *gp, *accp;
    cudaGetSymbolAddress((void**)&gp, d_g);
    cudaGetSymbolAddress((void**)&accp, d_acc);

    // degree + CSR build (reused by all 4 layers)
    k_zero_cnt<<<NB, 256>>>();
    k_count<<<(EE + 255) / 256, 256>>>(dstp);
    k_dinv<<<NB, 256>>>();
    k_scan1<<<NB, 256>>>();
    k_scan2<<<1, 512>>>();
    k_scan3<<<NB, 256>>>();
    k_fill<<<(EE + 255) / 256, 256>>>(srcp, dstp);

    // layer 0
    k_gemm0<<<1024, 256>>>(x, W0);
    k_gather<<<NN / 8, 256>>>();

    // layers 1..3 (bias+relu+dinv of prev layer fused into GEMM input transform)
    k_wconv<<<64, 256>>>(W1);
    k_gemm_mma<<<GTILES, 256, SMEM_MMA>>>(accp, b0, gp);
    k_gather<<<NN / 8, 256>>>();

    k_wconv<<<64, 256>>>(W2);
    k_gemm_mma<<<GTILES, 256, SMEM_MMA>>>(accp, b1, gp);
    k_gather<<<NN / 8, 256>>>();

    k_wconv<<<64, 256>>>(W3);
    k_gemm_mma<<<GTILES, 256, SMEM_MMA>>>(accp, b2, gp);
    k_gather<<<NN / 8, 256>>>();

    // pool + head
    k_zero_pool<<<(GG * 128 + 255) / 256, 256>>>();
    k_pool<<<NN * 32 / 256, 256>>>(batch, b3);
    k_mlp<<<GG, 64>>>(xs, Wl1, bl1, Wl2, bl2, out);
}